// round 14
// baseline (speedup 1.0000x reference)
#include <cuda_runtime.h>
#include <cstdint>

#define BB 1024
#define LL 512
#define TT 64

typedef unsigned long long ull;

// ---- packed f32x2 helpers (sm_103a; ptxas never emits these from C++) ----
__device__ __forceinline__ ull packf2(float lo, float hi) {
    ull r; asm("mov.b64 %0, {%1, %2};" : "=l"(r) : "f"(lo), "f"(hi)); return r;
}
__device__ __forceinline__ void unpackf2(ull v, float& lo, float& hi) {
    asm("mov.b64 {%0, %1}, %2;" : "=f"(lo), "=f"(hi) : "l"(v));
}
__device__ __forceinline__ ull fma2(ull a, ull b, ull c) {
    ull d; asm("fma.rn.f32x2 %0, %1, %2, %3;" : "=l"(d) : "l"(a), "l"(b), "l"(c)); return d;
}
__device__ __forceinline__ ull add2(ull a, ull b) {
    ull d; asm("add.rn.f32x2 %0, %1, %2;" : "=l"(d) : "l"(a), "l"(b)); return d;
}

// ---------------------------------------------------------------------------
// Fused CRF NLL kernel.  TWO warps per batch row (each warp owns 32 columns,
// one column per lane); 7 rows = 14 warps per CTA; 148 CTAs (one wave).
// Forward recursion in scaled linear space:  alpha[b,j] = s + ln(u_j).
// Lazy renorm: every 4th applied step each warp publishes its half-max to
// SMEM; the combined scale is applied at the NEXT applied step (off the
// critical path, cross-warp max rides the per-step __syncthreads).
// ---------------------------------------------------------------------------
__global__ __launch_bounds__(448, 1)
void crf_kernel(const float* __restrict__ logits,
                const int* __restrict__ tags,
                const int* __restrict__ mask,
                const float* __restrict__ trans,
                float* __restrict__ out)
{
    __shared__ __align__(16) float buf[2][7][TT];   // double-buffered alpha (linear)
    __shared__ __align__(8)  float hm[7][2];        // per-row half maxima / final sums

    int w    = threadIdx.x >> 5;
    int lane = threadIdx.x & 31;
    int r    = w >> 1;           // row within CTA
    int half = w & 1;            // which 32-column half this warp owns

    int nb = blockIdx.x, b0, nrows;
    if (nb < 136) { b0 = nb * 7;               nrows = 7; }
    else          { b0 = 952 + (nb - 136) * 6; nrows = 6; }
    if (r >= nrows) return;      // whole-warp exit (excluded from __syncthreads)
    int b = b0 + r;
    int j = half * 32 + lane;    // owned output column

    const float* lg = logits + (size_t)b * (LL * TT);
    const int*   mp = mask   + (size_t)b * LL;

    // ---- gold path score (warp-even only; overlaps with M setup) ----------
    float gacc = 0.f;
    if (half == 0) {
        const int* tg = tags + (size_t)b * LL;
        #pragma unroll 4
        for (int p = lane; p < LL; p += 32) {
            int   t0 = tg[p];
            float m0 = (mp[p] > 0) ? 1.f : 0.f;
            gacc += lg[p * TT + t0] * m0;
            if (p + 1 < LL) {
                int   t1 = tg[p + 1];
                float m1 = (mp[p + 1] > 0) ? 1.f : 0.f;
                gacc += trans[t0 * TT + t1] * m1;
            }
        }
        #pragma unroll
        for (int o = 16; o; o >>= 1) gacc += __shfl_xor_sync(0xffffffffu, gacc, o);
    }

    // ---- M column j of exp(trans), packed over k (32 x f32x2) -------------
    ull M[32];
    #pragma unroll
    for (int p = 0; p < 32; p++) {
        M[p] = packf2(__expf(trans[(2 * p) * TT + j]),
                      __expf(trans[(2 * p + 1) * TT + j]));
    }

    // ---- init l=0: alpha0 = emit0 ----------------------------------------
    float u = __expf(lg[j]);
    float s = 0.f;
    int cnt = 1, cur = 0, pend = 0;
    buf[0][r][j] = u;

    // ---- 2-deep emission/mask prefetch -----------------------------------
    float e1 = lg[TT + j];      int mk1 = mp[1];
    float e2 = lg[2 * TT + j];  int mk2 = mp[2];
    __syncthreads();

    for (int l = 1; l < LL; l++) {
        float e = e1; int mk = mk1;
        e1 = e2; mk1 = mk2;
        if (l + 2 < LL) {
            e2  = __ldg(&lg[(size_t)(l + 2) * TT + j]);
            mk2 = __ldg(&mp[l + 2]);
        }

        if (mk > 0) {                       // warp-uniform (per-row) branch
            float E = __expf(e);

            // dot_j = sum_k u_k * M[k][j]  (k packed in pairs; 4 chains of 8)
            ull a0 = 0, a1 = 0, a2 = 0, a3 = 0;
            const ulonglong2* uv = (const ulonglong2*)buf[cur][r];
            #pragma unroll
            for (int i = 0; i < 8; i++) {
                ulonglong2 p0 = uv[2 * i];      // broadcast LDS.128
                ulonglong2 p1 = uv[2 * i + 1];
                a0 = fma2(p0.x, M[4 * i + 0], a0);
                a1 = fma2(p0.y, M[4 * i + 1], a1);
                a2 = fma2(p1.x, M[4 * i + 2], a2);
                a3 = fma2(p1.y, M[4 * i + 3], a3);
            }
            ull sp = add2(add2(a0, a2), add2(a1, a3));
            float lo, hi; unpackf2(sp, lo, hi);
            float dot = lo + hi;

            if (pend) {                     // apply deferred renorm scale
                float2 h = *(const float2*)hm[r];
                float  m = fmaxf(h.x, h.y);
                dot *= __fdividef(1.0f, m);
                if (half == 0 && lane == 0) s += __logf(m);
                pend = 0;
            }
            u = dot * E;

            if (++cnt >= 4) {               // publish half-max; apply next time
                float mm = u;
                #pragma unroll
                for (int o = 16; o; o >>= 1)
                    mm = fmaxf(mm, __shfl_xor_sync(0xffffffffu, mm, o));
                if (lane == 0) hm[r][half] = mm;
                pend = 1; cnt = 0;
            }

            cur ^= 1;
            buf[cur][r][j] = u;             // STS.32, conflict-free
        }
        // mask==0: alpha carried (buf[cur], u, s, pend unchanged)
        __syncthreads();                    // uniform: outside the mask branch
    }

    // ---- logZ = s + ln(sum_j u_j); out = logZ - gold ----------------------
    float tot = u;
    #pragma unroll
    for (int o = 16; o; o >>= 1) tot += __shfl_xor_sync(0xffffffffu, tot, o);
    if (lane == 0) hm[r][half] = tot;       // reuse hm for half-sums
    __syncthreads();
    if (half == 0 && lane == 0)
        out[b] = s + __logf(hm[r][0] + hm[r][1]) - gacc;
}

extern "C" void kernel_launch(void* const* d_in, const int* in_sizes, int n_in,
                              void* d_out, int out_size)
{
    const float* logits = (const float*)d_in[0];
    const int*   tags   = (const int*)d_in[1];
    const int*   mask   = (const int*)d_in[2];
    const float* trans  = (const float*)d_in[3];
    float*       out    = (float*)d_out;

    crf_kernel<<<148, 448>>>(logits, tags, mask, trans, out);
}